// round 8
// baseline (speedup 1.0000x reference)
#include <cuda_runtime.h>
#include <cuda_bf16.h>
#include <cstdint>

// PositionAwarePooling: x [B=32, C=128, H=128, W=128] f32
// 2x2 non-overlapping maxpool + argmax position -> out [B, 3C, 64, 64]
// One thread = TWO adjacent windows (one float4 per input row).
// Streaming cache hints (.cs) on loads and stores (zero reuse).
// Block = 1024 (vs 512 in R7): halves CTA count again -> shorter dispatch ramp.

#define B_ 32
#define C_ 128
#define H_ 128
#define W_ 128
#define OH 64
#define OW 64
#define INV_HW 0.0078125f   // 1/128 exact

__global__ __launch_bounds__(1024) void pap_kernel(
    const float* __restrict__ x, float* __restrict__ out)
{
    // tid covers (b, c, oh, ow2) with ow2 in [0,32): pair of windows
    int tid = blockIdx.x * blockDim.x + threadIdx.x;
    // total = 32*128*64*32 = 8388608
    int ow2 = tid & 31;
    int t1  = tid >> 5;
    int oh  = t1 & 63;
    int t2  = t1 >> 6;
    int c   = t2 & 127;
    int b   = t2 >> 7;

    const float* base = x + (((size_t)(b * C_ + c) * H_) + 2 * oh) * W_ + 4 * ow2;
    float4 r0 = __ldcs(reinterpret_cast<const float4*>(base));
    float4 r1 = __ldcs(reinterpret_cast<const float4*>(base + W_));

    // window 0: r0.x r0.y / r1.x r1.y  (first-max via strict >)
    float v0 = r0.x; int i0 = 0;
    if (r0.y > v0) { v0 = r0.y; i0 = 1; }
    if (r1.x > v0) { v0 = r1.x; i0 = 2; }
    if (r1.y > v0) { v0 = r1.y; i0 = 3; }

    // window 1: r0.z r0.w / r1.z r1.w
    float v1 = r0.z; int i1 = 0;
    if (r0.w > v1) { v1 = r0.w; i1 = 1; }
    if (r1.z > v1) { v1 = r1.z; i1 = 2; }
    if (r1.w > v1) { v1 = r1.w; i1 = 3; }

    int row0 = 2 * oh + (i0 >> 1);
    int row1 = 2 * oh + (i1 >> 1);
    int col0 = 4 * ow2 + (i0 & 1);
    int col1 = 4 * ow2 + 2 + (i1 & 1);

    float2 vals = make_float2(v0, v1);
    float2 ph   = make_float2((float)row0 * INV_HW, (float)row1 * INV_HW);
    float2 pw   = make_float2((float)col0 * INV_HW, (float)col1 * INV_HW);

    size_t plane = (size_t)OH * OW;                 // 4096
    size_t obase = ((size_t)(b * 3 * C_ + c) * plane) + (size_t)oh * OW + 2 * ow2;
    __stcs(reinterpret_cast<float2*>(out + obase),                  vals);
    __stcs(reinterpret_cast<float2*>(out + obase + C_ * plane),     ph);
    __stcs(reinterpret_cast<float2*>(out + obase + 2 * C_ * plane), pw);
}

extern "C" void kernel_launch(void* const* d_in, const int* in_sizes, int n_in,
                              void* d_out, int out_size)
{
    const float* x = (const float*)d_in[0];
    float* out = (float*)d_out;
    int total_threads = B_ * C_ * OH * (OW / 2);   // 8388608
    int block = 1024;
    int grid = total_threads / block;              // 8192
    pap_kernel<<<grid, block>>>(x, out);
}